// round 16
// baseline (speedup 1.0000x reference)
#include <cuda_runtime.h>

#define KW 7
#define PAD 3
#define H 480
#define W 640
#define NB 4
#define HW (H * W)
#define TX 32
#define TY 8
#define TILE_W (TX + 2 * PAD)   // 38
#define TILE_H (TY + 2 * PAD)   // 14
// exponent constant: -1/(2*0.1^2) * log2(e) = -50 * log2(e)
#define NEG50_LOG2E (-72.13475204444817f)
#define EBIAS 4.0f               // weights scaled by 2^4: cancels in num/den

typedef unsigned long long u64;

__device__ __forceinline__ u64 pk(float lo, float hi) {
    u64 r; asm("mov.b64 %0, {%1, %2};" : "=l"(r) : "f"(lo), "f"(hi)); return r;
}
__device__ __forceinline__ void upk(float& lo, float& hi, u64 v) {
    asm("mov.b64 {%0, %1}, %2;" : "=f"(lo), "=f"(hi) : "l"(v));
}
__device__ __forceinline__ u64 add2(u64 a, u64 b) {
    u64 r; asm("add.rn.f32x2 %0, %1, %2;" : "=l"(r) : "l"(a), "l"(b)); return r;
}
__device__ __forceinline__ u64 mul2(u64 a, u64 b) {
    u64 r; asm("mul.rn.f32x2 %0, %1, %2;" : "=l"(r) : "l"(a), "l"(b)); return r;
}
__device__ __forceinline__ u64 fma2(u64 a, u64 b, u64 c) {
    u64 r; asm("fma.rn.f32x2 %0, %1, %2, %3;" : "=l"(r) : "l"(a), "l"(b), "l"(c)); return r;
}

// Weight pair: q01 holds (d0^2, d1^2) as f32x2. Returns (2^(C*q+lg'), ...) as
// f32x2, where lg' = log2(g)+4 (pre-packed f16x2) and C = -50*log2(e) (f16x2).
// XU cost: 1 pack-cvt + 1 ex2.f16x2. HFMA2 on fma pipe. f16->f32 unpack done
// with integer ops (exact for normal f16; biased +4 so subnormals are
// negligible: error <= 2^-18 per weight).
__device__ __forceinline__ u64 wpair(u64 q01, unsigned lgh, unsigned Ch) {
    float q0, q1;
    upk(q0, q1, q01);
    unsigned ph, eh, wh;
    asm("cvt.rn.f16x2.f32 %0, %2, %1;" : "=r"(ph) : "f"(q0), "f"(q1)); // hi=q1 lo=q0
    asm("fma.rn.f16x2 %0, %1, %2, %3;" : "=r"(eh) : "r"(Ch), "r"(ph), "r"(lgh));
    asm("ex2.approx.f16x2 %0, %1;" : "=r"(wh) : "r"(eh));
    const unsigned wlo = ((wh & 0xFFFFu) << 13) + 0x38000000u;
    const unsigned whi = ((wh >> 16) << 13) + 0x38000000u;
    return pk(__uint_as_float(wlo), __uint_as_float(whi));
}

__global__ __launch_bounds__(TX * TY, 8) void bilateral_kernel(
    const float* __restrict__ I,
    const float* __restrict__ g,
    float* __restrict__ out)
{
    __shared__ ulonglong2 tile[TILE_H][TILE_W];   // batch-interleaved, 8512 B
    __shared__ unsigned lg2s[KW * KW];            // f16x2(log2(g)+4) per tap

    const int x0 = blockIdx.x * TX;
    const int y0 = blockIdx.y * TY;
    const int tx = threadIdx.x;
    const int ty = threadIdx.y;
    const int tid = ty * TX + tx;

    if (tid < KW * KW) {
        const float lv = __log2f(__ldg(g + tid * HW)) + EBIAS;
        unsigned lh;
        asm("cvt.rn.f16x2.f32 %0, %1, %1;" : "=r"(lh) : "f"(lv));
        lg2s[tid] = lh;
    }

    // Halo tile load (zero pad outside image), batch-interleaved.
    for (int i = tid; i < TILE_H * TILE_W; i += TX * TY) {
        const int ly = i / TILE_W;
        const int lx = i - ly * TILE_W;
        const int gy = y0 + ly - PAD;
        const int gx = x0 + lx - PAD;
        float4 v = make_float4(0.f, 0.f, 0.f, 0.f);
        if (gy >= 0 && gy < H && gx >= 0 && gx < W) {
            const int base = gy * W + gx;
            v.x = I[0 * HW + base];
            v.y = I[1 * HW + base];
            v.z = I[2 * HW + base];
            v.w = I[3 * HW + base];
        }
        *reinterpret_cast<float4*>(&tile[ly][lx]) = v;   // STS.128
    }
    __syncthreads();

    unsigned Ch;   // f16x2(-72.1347, -72.1347)
    asm("cvt.rn.f16x2.f32 %0, %1, %1;" : "=r"(Ch) : "f"(NEG50_LOG2E));

    const ulonglong2 cc = tile[ty + PAD][tx + PAD];
    float c0, c1, c2, c3;
    upk(c0, c1, cc.x);
    upk(c2, c3, cc.y);
    const u64 nc01 = pk(-c0, -c1);
    const u64 nc23 = pk(-c2, -c3);

    u64 num01 = 0ull, num23 = 0ull, den01 = 0ull, den23 = 0ull;

    #pragma unroll
    for (int dy = 0; dy < KW; dy++) {
        #pragma unroll
        for (int dx = 0; dx < KW; dx++) {
            const ulonglong2 s = tile[ty + dy][tx + dx];   // LDS.128
            const unsigned lgh = lg2s[dy * KW + dx];       // LDS.32 bcast

            const u64 d01 = add2(s.x, nc01);
            const u64 d23 = add2(s.y, nc23);
            const u64 q01 = mul2(d01, d01);
            const u64 q23 = mul2(d23, d23);

            const u64 w01 = wpair(q01, lgh, Ch);
            const u64 w23 = wpair(q23, lgh, Ch);

            den01 = add2(den01, w01);
            den23 = add2(den23, w23);
            num01 = fma2(w01, s.x, num01);
            num23 = fma2(w23, s.y, num23);
        }
    }

    float n0, n1, n2, n3, de0, de1, de2, de3;
    upk(n0, n1, num01); upk(n2, n3, num23);
    upk(de0, de1, den01); upk(de2, de3, den23);

    const int oidx = (y0 + ty) * W + (x0 + tx);
    out[0 * HW + oidx] = __fdividef(n0, de0);
    out[1 * HW + oidx] = __fdividef(n1, de1);
    out[2 * HW + oidx] = __fdividef(n2, de2);
    out[3 * HW + oidx] = __fdividef(n3, de3);
}

extern "C" void kernel_launch(void* const* d_in, const int* in_sizes, int n_in,
                              void* d_out, int out_size)
{
    const float* I = (const float*)d_in[0];
    const float* g = (const float*)d_in[1];
    float* out = (float*)d_out;

    dim3 block(TX, TY);
    dim3 grid(W / TX, H / TY);   // 20 x 60, exact
    bilateral_kernel<<<grid, block>>>(I, g, out);
}